// round 12
// baseline (speedup 1.0000x reference)
#include <cuda_runtime.h>

// ============================================================================
// Linear slab model, closed-form parallel solution (z_init = 0 exploited).
//   z_{n+1} = a*z_n + f_n,  a = (1-dt*K1) - i*dt*fc,  f_n linear per interval.
// Interval closed form (ns steps, f = p + q*m):
//   z_m = u + v*m + a^m*w,  v = q/(1-a), u = (p-v)/(1-a), w = z_start - u
// z_start(s) = sum_{j<s} A^{s-1-j} S_j,  A = a^ns.  |A|^512 <~ 1e-9 =>
// each 1024-interval block reconstructs its start exactly (f32) from a
// 512-interval recomputed halo.  TWO kernels, overlapped via PDL:
//   kAF: per-interval (u,v,S), halo reduction, block scan -> g_uv, g_w
//   kD : launched with ProgrammaticStreamSerialization; computes ALL consts
//        and index math from raw harness inputs pre-sync (overlapping kAF),
//        then cudaGridDependencySynchronize() and gathers g_uv/g_w only.
//        8 outputs/thread as two coalesced float4 windows.
// ============================================================================

#define SCAN_B 1024
#define MAXI   262144
#define NBLK   (MAXI / SCAN_B)   // 256
#define HALO   512
#define NW     2                 // windows per kD thread

__device__ float4 g_uv[MAXI];    // (u.x, u.y, v.x, v.y)
__device__ float2 g_w[MAXI];     // w per interval

__device__ __forceinline__ float2 cmul(float2 a, float2 b) {
    return make_float2(fmaf(a.x, b.x, -a.y * b.y), fmaf(a.x, b.y, a.y * b.x));
}
__device__ __forceinline__ float2 cfma2(float2 A, float2 z, float2 h) {
    return make_float2(fmaf(A.x, z.x, fmaf(-A.y, z.y, h.x)),
                       fmaf(A.x, z.y, fmaf( A.y, z.x, h.y)));
}
__device__ __forceinline__ float2 cpow(float2 a, int e) {
    float2 r = make_float2(1.0f, 0.0f);
    while (e) { if (e & 1) r = cmul(r, a); a = cmul(a, a); e >>= 1; }
    return r;
}
__device__ __forceinline__ float2 cinv(float2 a) {
    float s = 1.0f / fmaf(a.x, a.x, a.y * a.y);
    return make_float2(a.x * s, -a.y * s);
}

// A^e from tables: sA32[k] = A^{32k}, sLane[i] = A^{i+1}; e in [0, 1024)
__device__ __forceinline__ float2 apow_tab(int e, const float2* sLane,
                                           const float2* sA32) {
    float2 r = sA32[e >> 5];
    int lo = e & 31;
    if (lo) r = cmul(r, sLane[lo - 1]);
    return r;
}

// (u,v,S) for interval s
__device__ __forceinline__ void interval_op(
    int s, int j0, int nl, int ns, int m0, float e, float inv_ns,
    float2 a, float2 A, float2 inv1ma,
    const float* __restrict__ TAx, const float* __restrict__ TAy,
    float2& u, float2& v, float2& S)
{
    int j  = j0 + s;
    int i1 = min(j,     nl - 1);
    int i2 = min(j + 1, nl - 1);
    float Tx0 = __ldg(TAx + i1), Tx1 = __ldg(TAx + i2);
    float Ty0 = __ldg(TAy + i1), Ty1 = __ldg(TAy + i2);
    float2 p = make_float2(e * Tx0, e * Ty0);
    float  eq = e * inv_ns;
    float2 q = make_float2(eq * (Tx1 - Tx0), eq * (Ty1 - Ty0));
    v = cmul(q, inv1ma);
    u = cmul(make_float2(p.x - v.x, p.y - v.y), inv1ma);
    int    msta = (s == 0) ? m0 : 0;
    float2 P    = (msta == 0) ? A : cpow(a, ns - msta);
    float fns = (float)ns, fm = (float)msta;
    float2 zend = make_float2(fmaf(v.x, fns, u.x), fmaf(v.y, fns, u.y));
    float2 zsta = make_float2(fmaf(v.x, fm,  u.x), fmaf(v.y, fm,  u.y));
    float2 Ps   = cmul(P, zsta);
    S = make_float2(zend.x - Ps.x, zend.y - Ps.y);
}

// ---------------- kAF: fused setup (per-interval u,v,w) ----------------------
__global__ __launch_bounds__(SCAN_B) void kAF(
    const float* __restrict__ pk,
    const float* __restrict__ TAx, const float* __restrict__ TAy,
    const float* __restrict__ fcp,
    const int* __restrict__ t0p, const int* __restrict__ dtp,
    int nl, int nsteps)
{
    __shared__ float2 sLane[32];   // A^1 .. A^32
    __shared__ float2 sA32[32];    // A^{32k}
    __shared__ float2 wAgg[32];
    __shared__ float2 sS[SCAN_B];
    __shared__ float2 sZ;          // halo total = z at block start

    const int tid  = threadIdx.x;
    const int lane = tid & 31;
    const int wrp  = tid >> 5;

    const int   dti = dtp[0];
    const float dtf = (float)dti;
    const float c   = 1.0f - dtf * expf(pk[1]);
    const float d   = dtf * fcp[0];
    const float e   = dtf * expf(pk[0]);
    const int   ns  = 3600 / dti;
    const float inv_ns = 1.0f / (float)ns;
    const int   it0 = t0p[0] / dti;
    const int   j0  = it0 / ns;
    const int   m0  = it0 - j0 * ns;
    const int   NI  = (m0 + nsteps + ns - 1) / ns;
    const float2 a  = make_float2(c, -d);
    const float2 inv1ma = cinv(make_float2(1.0f - c, d));
    const float2 A  = cpow(a, ns);

    const int s0 = blockIdx.x * SCAN_B;
    if (s0 >= NI) return;          // uniform early exit (before any sync)

    if (tid < 32)       sLane[tid]     = cpow(A, tid + 1);
    else if (tid < 64)  sA32[tid - 32] = cpow(A, (tid - 32) * 32);

    const int  s = s0 + tid;
    const bool valid = (s < NI);
    float2 u, v, S;
    interval_op(s, j0, nl, ns, m0, e, inv_ns, a, A, inv1ma, TAx, TAy, u, v, S);
    if (valid) g_uv[s] = make_float4(u.x, u.y, v.x, v.y);
    if (!valid) S = make_float2(0.0f, 0.0f);

    float2 Sh = make_float2(0.0f, 0.0f);
    const bool hash = (blockIdx.x > 0) && (tid < HALO);
    if (hash) {
        float2 uh, vh;
        interval_op(s0 - HALO + tid, j0, nl, ns, m0, e, inv_ns, a, A, inv1ma,
                    TAx, TAy, uh, vh, Sh);
    }
    __syncthreads();               // tables ready

    float2 ht = make_float2(0.0f, 0.0f);
    if (hash) ht = cmul(apow_tab(HALO - 1 - tid, sLane, sA32), Sh);
    const unsigned fullm = 0xffffffffu;
#pragma unroll
    for (int off = 16; off > 0; off >>= 1) {
        ht.x += __shfl_down_sync(fullm, ht.x, off);
        ht.y += __shfl_down_sync(fullm, ht.y, off);
    }
    if (lane == 0) wAgg[wrp] = ht;
    __syncthreads();
    if (wrp == 0) {
        float2 r2 = wAgg[lane];
#pragma unroll
        for (int off = 16; off > 0; off >>= 1) {
            r2.x += __shfl_down_sync(fullm, r2.x, off);
            r2.y += __shfl_down_sync(fullm, r2.y, off);
        }
        if (lane == 0) sZ = r2;
    }
    __syncthreads();               // sZ ready; wAgg reusable

    float2 Sc = S;
#pragma unroll
    for (int rk = 0; rk < 5; rk++) {
        int off = 1 << rk;
        float2 M = sLane[off - 1];
        float px = __shfl_up_sync(fullm, Sc.x, off);
        float py = __shfl_up_sync(fullm, Sc.y, off);
        if (lane >= off) Sc = cfma2(M, make_float2(px, py), Sc);
    }
    if (lane == 31) wAgg[wrp] = Sc;
    __syncthreads();
    if (wrp == 0) {
        float2 T = wAgg[lane];
#pragma unroll
        for (int rk = 0; rk < 5; rk++) {
            int off = 1 << rk;
            float2 M = sA32[off];                   // A^{32*off}
            float px = __shfl_up_sync(fullm, T.x, off);
            float py = __shfl_up_sync(fullm, T.y, off);
            if (lane >= off) T = cfma2(M, make_float2(px, py), T);
        }
        wAgg[lane] = T;
    }
    __syncthreads();
    if (wrp > 0) Sc = cfma2(sLane[lane], wAgg[wrp - 1], Sc);
    sS[tid] = Sc;
    __syncthreads();

    if (valid) {
        float2 Ex  = (tid > 0) ? sS[tid - 1] : make_float2(0.0f, 0.0f);
        float2 Apt = apow_tab(tid, sLane, sA32);
        float2 zst = cfma2(Apt, sZ, Ex);            // state at interval start
        float2 w;
        if (s == 0 && m0 != 0) {
            w = make_float2(zst.x - fmaf(v.x, (float)m0, u.x),
                            zst.y - fmaf(v.y, (float)m0, u.y));
            w = cmul(w, cinv(cpow(a, m0)));
        } else {
            w = make_float2(zst.x - u.x, zst.y - u.y);
        }
        g_w[s] = w;
    }
}

// ---------------- kD ----------------------------------------------------------
// scalar fallback with crossing handling (tail / odd-parameter cases only)
__device__ __noinline__ void slow_window(
    int n0, int nsteps, int ns, int it0, int j0, float2 a,
    float* __restrict__ out)
{
    const int it = it0 + n0;
    const int sg = it / ns;
    int r    = it - sg * ns;
    int sidx = sg - j0;

    float4 uv = __ldg(g_uv + sidx);
    float2 w  = __ldg(g_w  + sidx);
    int m = r + 1;
    float2 aw = cmul(cpow(a, m), w);
    float  fm = (float)m;
    float2 base = make_float2(fmaf(uv.z, fm, uv.x), fmaf(uv.w, fm, uv.y));
    int lim = min(4, nsteps - n0);
    for (int kk = 0; kk < lim; kk++) {
        float2 z = make_float2(base.x + aw.x, base.y + aw.y);
        out[n0 + kk]          = z.x;
        out[nsteps + n0 + kk] = z.y;
        if (kk + 1 < lim) {
            if (m == ns) {
                sidx = min(sidx + 1, MAXI - 1);
                uv = __ldg(g_uv + sidx);
                w  = make_float2(z.x - uv.x, z.y - uv.y);
                m  = 1;
                base = make_float2(uv.x + uv.z, uv.y + uv.w);
                aw   = cmul(a, w);
            } else {
                m++;
                base.x += uv.z; base.y += uv.w;
                aw = cmul(aw, a);
            }
        }
    }
}

__global__ __launch_bounds__(256) void kD(
    const float* __restrict__ pk, const float* __restrict__ fcp,
    const int* __restrict__ t0p, const int* __restrict__ dtp,
    int nsteps, int ofs4, float* __restrict__ out)
{
    // ---- PRE-SYNC: everything from raw harness inputs (overlaps kAF) ----
    const int   dti = dtp[0];
    const float dtf = (float)dti;
    const float c   = 1.0f - dtf * expf(pk[1]);
    const float d   = dtf * fcp[0];
    const float2 a  = make_float2(c, -d);
    const int   ns  = 3600 / dti;
    const int   it0 = t0p[0] / dti;
    const int   j0  = it0 / ns;

    const int t  = blockIdx.x * blockDim.x + threadIdx.x;
    const int n0 = t * 4;
    if (n0 >= nsteps) return;

    const bool allfast = ((ns & 3) == 0) && ((it0 & 3) == 0) &&
                         ((nsteps & 3) == 0);

    int    nn[NW], rr[NW], si[NW];
    bool   act[NW];
    float2 pw[NW];
#pragma unroll
    for (int i = 0; i < NW; i++) {
        int n = n0 + i * ofs4;
        act[i] = (n + 4 <= nsteps);
        nn[i]  = act[i] ? n : 0;
        int it = it0 + nn[i];
        int sg = it / ns;
        rr[i]  = it - sg * ns;
        si[i]  = sg - j0;
        pw[i]  = cpow(a, rr[i] + 1);        // a^(r+1), local (no table dep)
    }

    // ---- wait for kAF's g_uv / g_w ----
    cudaGridDependencySynchronize();

    if (allfast) {
        // gather (MLP across windows)
        float4 uv[NW];
        float2 wv[NW];
#pragma unroll
        for (int i = 0; i < NW; i++) {
            uv[i] = __ldg(g_uv + si[i]);
            wv[i] = __ldg(g_w  + si[i]);
        }
        // compute + store (r%4==0: window never crosses an interval)
#pragma unroll
        for (int i = 0; i < NW; i++) {
            if (!act[i]) continue;
            float2 aw = cmul(pw[i], wv[i]);
            float  fm = (float)(rr[i] + 1);
            float2 base = make_float2(fmaf(uv[i].z, fm, uv[i].x),
                                      fmaf(uv[i].w, fm, uv[i].y));
            float4 Uq, Vq;
            Uq.x = base.x + aw.x; Vq.x = base.y + aw.y;
            base.x += uv[i].z; base.y += uv[i].w; aw = cmul(aw, a);
            Uq.y = base.x + aw.x; Vq.y = base.y + aw.y;
            base.x += uv[i].z; base.y += uv[i].w; aw = cmul(aw, a);
            Uq.z = base.x + aw.x; Vq.z = base.y + aw.y;
            base.x += uv[i].z; base.y += uv[i].w; aw = cmul(aw, a);
            Uq.w = base.x + aw.x; Vq.w = base.y + aw.y;
            *reinterpret_cast<float4*>(out + nn[i])          = Uq;
            *reinterpret_cast<float4*>(out + nsteps + nn[i]) = Vq;
        }
        // tail windows not covered by the fast path
#pragma unroll
        for (int i = 0; i < NW; i++) {
            int n = n0 + i * ofs4;
            if (n < nsteps && n + 4 > nsteps)
                slow_window(n, nsteps, ns, it0, j0, a, out);
        }
    } else {
#pragma unroll
        for (int i = 0; i < NW; i++) {
            int n = n0 + i * ofs4;
            if (n < nsteps) slow_window(n, nsteps, ns, it0, j0, a, out);
        }
    }
}

// ---------------- host ------------------------------------------------------
extern "C" void kernel_launch(void* const* d_in, const int* in_sizes, int n_in,
                              void* d_out, int out_size)
{
    const float* pk  = (const float*)d_in[0];
    const float* TAx = (const float*)d_in[1];
    const float* TAy = (const float*)d_in[2];
    const float* fcp = (const float*)d_in[3];
    const int*   t0p = (const int*)d_in[4];
    // d_in[5] = t1 (unused; nsteps derived from out_size)
    const int*   dtp = (const int*)d_in[6];

    const int nl     = in_sizes[1];
    const int nsteps = out_size / 2;
    float* out = (float*)d_out;

    kAF<<<NBLK, SCAN_B>>>(pk, TAx, TAy, fcp, t0p, dtp, nl, nsteps);

    const int TB   = 256;
    const int nthr = (nsteps + NW * 4 - 1) / (NW * 4);   // 8 outputs/thread
    const int ofs4 = nthr * 4;
    const int GB   = (nthr + TB - 1) / TB;

    // PDL: kD launches concurrently with kAF; its pre-sync phase uses only
    // harness inputs, then cudaGridDependencySynchronize() gates the gathers.
    cudaLaunchConfig_t cfg = {};
    cfg.gridDim  = dim3((unsigned)GB);
    cfg.blockDim = dim3((unsigned)TB);
    cfg.dynamicSmemBytes = 0;
    cfg.stream = 0;
    cudaLaunchAttribute attr[1];
    attr[0].id = cudaLaunchAttributeProgrammaticStreamSerialization;
    attr[0].val.programmaticStreamSerializationAllowed = 1;
    cfg.attrs = attr;
    cfg.numAttrs = 1;
    cudaLaunchKernelEx(&cfg, kD, pk, fcp, t0p, dtp, nsteps, ofs4, out);
}